// round 2
// baseline (speedup 1.0000x reference)
#include <cuda_runtime.h>
#include <cstdint>
#include <cstddef>

// ---------------- problem constants ----------------
constexpr int N_  = 16;
constexpr int D_  = 16;
constexpr int S_  = 112;
constexpr int SS_ = S_ * S_;          // 12544
constexpr int M_  = 2;
constexpr int V_  = 7829;
constexpr int K_  = 512;
constexpr int NM_ = N_ * M_;          // 32
constexpr int NCH = 8;                // v-chunks for row passes
constexpr int VCH = (V_ + NCH - 1) / NCH;   // 979
constexpr int NPAIR = 10;             // lower-tri 128-tile pairs of a 4x4 grid
constexpr float TSCALE = 20.0f;       // 1/T
constexpr float BETA   = 42.0f;       // stability shift

// ---------------- static device scratch ----------------
__device__ float g_sim[(size_t)NM_ * V_ * K_];    // [nm][v][k]
__device__ float g_Et [(size_t)NM_ * V_ * K_];    // [nm][v][k]
__device__ float g_sampled[N_ * K_ * D_];
__device__ float g_fx[N_ * K_], g_fy[N_ * K_];
__device__ float g_rpmax[NM_ * NCH * K_];
__device__ float g_rpsum[NM_ * NCH * K_];
__device__ float g_tk[NM_ * K_];      // -20*rmax[k]
__device__ float g_rk[NM_ * K_];      // 1/rsum[k]
__device__ float g_fq[NM_ * K_];      // exp(20*rmax[k] - 2*BETA)
__device__ float g_sv[NM_ * V_];      // BETA - 10*cmax[v] - 0.5*ln(csum[v])
__device__ float g_partial[NM_ * NPAIR];
__device__ int   g_is64;

// ---------------- fast exp: pure FMA, ~1.3e-6 rel err ----------------
static __device__ __forceinline__ float fexp(float x) {
    float y = x * 1.4426950408889634f;           // x/ln2
    y = fminf(y, 126.0f);
    if (y < -126.0f) return 0.0f;
    float fl = floorf(y);
    float f  = y - fl;                            // [0,1)
    float p = 1.5252733804e-5f;
    p = fmaf(p, f, 1.5403530393e-4f);
    p = fmaf(p, f, 1.3333558146e-3f);
    p = fmaf(p, f, 9.6181291076e-3f);
    p = fmaf(p, f, 5.5504108664e-2f);
    p = fmaf(p, f, 2.4022650696e-1f);
    p = fmaf(p, f, 6.9314718056e-1f);
    p = fmaf(p, f, 1.0f);
    return __int_as_float(__float_as_int(p) + (((int)fl) << 23));
}

// ---------------- K0: detect int64 vs int32 indices ----------------
__global__ void k_detect(const int* __restrict__ w) {
    __shared__ int s_allzero;
    if (threadIdx.x == 0) s_allzero = 1;
    __syncthreads();
    int nz = 0;
    for (int i = threadIdx.x * 2 + 1; i < N_ * K_; i += blockDim.x * 2)
        if (w[i] != 0) nz = 1;
    if (nz) atomicAnd(&s_allzero, 0);
    __syncthreads();
    if (threadIdx.x == 0) g_is64 = s_allzero;   // all odd 32-bit words zero => int64
}

// ---------------- K1: gather + normalize sampled embeddings ----------------
__global__ void k_sample(const float* __restrict__ pix, const void* __restrict__ idxraw) {
    int t = blockIdx.x * blockDim.x + threadIdx.x;
    if (t >= N_ * K_) return;
    long long idx;
    if (g_is64) idx = ((const long long*)idxraw)[t];
    else        idx = (long long)((const int*)idxraw)[t];
    int n = t / K_;
    int p = (int)idx;
    g_fx[t] = (float)(p / S_);
    g_fy[t] = (float)(p % S_);
    const float* base = pix + (size_t)n * D_ * SS_ + p;
    float v[16]; float ss = 0.f;
#pragma unroll
    for (int d = 0; d < 16; d++) { v[d] = base[(size_t)d * SS_]; ss = fmaf(v[d], v[d], ss); }
    float inv = 1.0f / fmaxf(sqrtf(ss), 1e-6f);
#pragma unroll
    for (int d = 0; d < 16; d++) g_sampled[t * 16 + d] = v[d] * inv;
}

// ---------------- K2: sim[nm][v][k] + per-chunk row max (over v) ----------------
__global__ void __launch_bounds__(512) k_sim(const float* __restrict__ mesh) {
    int nm = blockIdx.x, ch = blockIdx.y;
    int k  = threadIdx.x;
    int n = nm / M_, m = nm % M_;
    float sk[16];
    const float* sp = &g_sampled[(n * K_ + k) * 16];
#pragma unroll
    for (int d = 0; d < 16; d++) sk[d] = sp[d];
    int v0 = ch * VCH;
    int v1 = min(v0 + VCH, V_);
    float mx = -1e30f;
    float* simbase = g_sim + (size_t)nm * V_ * K_;
    const float4* mb = (const float4*)(mesh + (size_t)m * V_ * D_);
    for (int v = v0; v < v1; v++) {
        float4 m0 = mb[v * 4 + 0], m1 = mb[v * 4 + 1];
        float4 m2 = mb[v * 4 + 2], m3 = mb[v * 4 + 3];
        float s;
        s =          sk[0]  * m0.x;     s = fmaf(sk[1],  m0.y, s);
        s = fmaf(sk[2],  m0.z, s);      s = fmaf(sk[3],  m0.w, s);
        s = fmaf(sk[4],  m1.x, s);      s = fmaf(sk[5],  m1.y, s);
        s = fmaf(sk[6],  m1.z, s);      s = fmaf(sk[7],  m1.w, s);
        s = fmaf(sk[8],  m2.x, s);      s = fmaf(sk[9],  m2.y, s);
        s = fmaf(sk[10], m2.z, s);      s = fmaf(sk[11], m2.w, s);
        s = fmaf(sk[12], m3.x, s);      s = fmaf(sk[13], m3.y, s);
        s = fmaf(sk[14], m3.z, s);      s = fmaf(sk[15], m3.w, s);
        simbase[(size_t)v * K_ + k] = s;
        mx = fmaxf(mx, s);
    }
    g_rpmax[(nm * NCH + ch) * K_ + k] = mx;
}

// ---------------- K2b: combine chunk maxes -> tk ----------------
__global__ void k_rowmax() {
    int t = blockIdx.x * blockDim.x + threadIdx.x;
    if (t >= NM_ * K_) return;
    int nm = t / K_, k = t % K_;
    float mx = -1e30f;
#pragma unroll
    for (int c = 0; c < NCH; c++) mx = fmaxf(mx, g_rpmax[(nm * NCH + c) * K_ + k]);
    g_tk[t] = -TSCALE * mx;
}

// ---------------- K2c: per-chunk row sums (needs final tk) ----------------
__global__ void __launch_bounds__(512) k_rowsum() {
    int nm = blockIdx.x, ch = blockIdx.y;
    int k  = threadIdx.x;
    float tk = g_tk[nm * K_ + k];
    int v0 = ch * VCH;
    int v1 = min(v0 + VCH, V_);
    const float* simbase = g_sim + (size_t)nm * V_ * K_;
    float s = 0.f;
    for (int v = v0; v < v1; v++)
        s += fexp(fmaf(TSCALE, simbase[(size_t)v * K_ + k], tk));
    g_rpsum[(nm * NCH + ch) * K_ + k] = s;
}

// ---------------- K2d: finalize rows -> rk, fq ----------------
__global__ void k_rowfin() {
    int t = blockIdx.x * blockDim.x + threadIdx.x;
    if (t >= NM_ * K_) return;
    int nm = t / K_, k = t % K_;
    float s = 0.f;
#pragma unroll
    for (int c = 0; c < NCH; c++) s += g_rpsum[(nm * NCH + c) * K_ + k];
    g_rk[t] = 1.0f / s;
    g_fq[t] = fexp(-g_tk[t] - 2.0f * BETA);
}

// ---------------- K3: column (over k) stats -> sv[v] ----------------
__global__ void k_colstats() {
    int nm = blockIdx.x;
    int v  = blockIdx.y * 8 + (threadIdx.x >> 5);
    int lane = threadIdx.x & 31;
    if (v >= V_) return;
    const float4* row = (const float4*)(g_sim + ((size_t)nm * V_ + v) * K_);
    float4 a = row[lane], b = row[lane + 32], c = row[lane + 64], d = row[lane + 96];
    float mx = fmaxf(fmaxf(fmaxf(a.x, a.y), fmaxf(a.z, a.w)),
               fmaxf(fmaxf(fmaxf(b.x, b.y), fmaxf(b.z, b.w)),
               fmaxf(fmaxf(fmaxf(c.x, c.y), fmaxf(c.z, c.w)),
                     fmaxf(fmaxf(d.x, d.y), fmaxf(d.z, d.w)))));
#pragma unroll
    for (int o = 16; o > 0; o >>= 1) mx = fmaxf(mx, __shfl_xor_sync(0xffffffffu, mx, o));
    float nmx = -TSCALE * mx;
    float s = fexp(fmaf(TSCALE, a.x, nmx)) + fexp(fmaf(TSCALE, a.y, nmx))
            + fexp(fmaf(TSCALE, a.z, nmx)) + fexp(fmaf(TSCALE, a.w, nmx))
            + fexp(fmaf(TSCALE, b.x, nmx)) + fexp(fmaf(TSCALE, b.y, nmx))
            + fexp(fmaf(TSCALE, b.z, nmx)) + fexp(fmaf(TSCALE, b.w, nmx))
            + fexp(fmaf(TSCALE, c.x, nmx)) + fexp(fmaf(TSCALE, c.y, nmx))
            + fexp(fmaf(TSCALE, c.z, nmx)) + fexp(fmaf(TSCALE, c.w, nmx))
            + fexp(fmaf(TSCALE, d.x, nmx)) + fexp(fmaf(TSCALE, d.y, nmx))
            + fexp(fmaf(TSCALE, d.z, nmx)) + fexp(fmaf(TSCALE, d.w, nmx));
#pragma unroll
    for (int o = 16; o > 0; o >>= 1) s += __shfl_xor_sync(0xffffffffu, s, o);
    if (lane == 0)
        g_sv[(size_t)nm * V_ + v] = BETA - 0.5f * TSCALE * mx - 0.5f * logf(s);
}

// ---------------- K4: Etilde = exp(20*sim + tk[k] + sv[v]) ----------------
__global__ void k_etilde() {
    size_t g = (size_t)blockIdx.x * blockDim.x + threadIdx.x;   // float4 id
    size_t e = g * 4;
    if (e >= (size_t)NM_ * V_ * K_) return;
    int    k  = (int)(e % K_);
    size_t vr = e / K_;
    int    nm = (int)(vr / V_);
    float sv = g_sv[vr];
    float4 tk4 = *(const float4*)&g_tk[nm * K_ + k];
    float4 s4  = *(const float4*)&g_sim[e];
    float4 o;
    o.x = fexp(fmaf(TSCALE, s4.x, tk4.x + sv));
    o.y = fexp(fmaf(TSCALE, s4.y, tk4.y + sv));
    o.z = fexp(fmaf(TSCALE, s4.z, tk4.z + sv));
    o.w = fexp(fmaf(TSCALE, s4.w, tk4.w + sv));
    *(float4*)&g_Et[e] = o;
}

// ---------------- K5: symmetric GEMM G = Et*Et^T per 128x128 pair + epilogue ----------------
__constant__ int c_ti[NPAIR] = {0,1,1,2,2,2,3,3,3,3};
__constant__ int c_tj[NPAIR] = {0,0,1,0,1,2,0,1,2,3};

__global__ void __launch_bounds__(256) k_gemm() {
    __shared__ float As[16][128];
    __shared__ float Bs[16][128];
    __shared__ float red[256];

    int nm = blockIdx.x, pr = blockIdx.y;
    int ti = c_ti[pr], tj = c_tj[pr];
    int n = nm / M_;
    int tid = threadIdx.x;
    int tx = tid & 15;           // col group (0..15)
    int ty = tid >> 4;           // row group (0..15)
    int r0 = tid >> 5;           // load row   (0..7)
    int c0 = (tid & 31) * 4;     // load col   (0..124)

    const float* EA = g_Et + (size_t)nm * V_ * K_ + ti * 128;
    const float* EB = g_Et + (size_t)nm * V_ * K_ + tj * 128;

    float acc[8][8];
#pragma unroll
    for (int i = 0; i < 8; i++)
#pragma unroll
        for (int j = 0; j < 8; j++) acc[i][j] = 0.f;

    const int NSTEP = (V_ + 15) / 16;
    for (int s = 0; s < NSTEP; s++) {
        int va = s * 16 + r0, vb = va + 8;
        float4 z = make_float4(0.f, 0.f, 0.f, 0.f);
        float4 a0 = (va < V_) ? *(const float4*)(EA + (size_t)va * K_ + c0) : z;
        float4 a1 = (vb < V_) ? *(const float4*)(EA + (size_t)vb * K_ + c0) : z;
        float4 b0 = (va < V_) ? *(const float4*)(EB + (size_t)va * K_ + c0) : z;
        float4 b1 = (vb < V_) ? *(const float4*)(EB + (size_t)vb * K_ + c0) : z;
        __syncthreads();
        *(float4*)&As[r0][c0]     = a0;
        *(float4*)&As[r0 + 8][c0] = a1;
        *(float4*)&Bs[r0][c0]     = b0;
        *(float4*)&Bs[r0 + 8][c0] = b1;
        __syncthreads();
#pragma unroll
        for (int kk = 0; kk < 16; kk++) {
            float ar[8], br[8];
            *(float4*)&ar[0] = *(const float4*)&As[kk][ty * 8];
            *(float4*)&ar[4] = *(const float4*)&As[kk][ty * 8 + 4];
            *(float4*)&br[0] = *(const float4*)&Bs[kk][tx * 8];
            *(float4*)&br[4] = *(const float4*)&Bs[kk][tx * 8 + 4];
#pragma unroll
            for (int i = 0; i < 8; i++)
#pragma unroll
                for (int j = 0; j < 8; j++)
                    acc[i][j] = fmaf(ar[i], br[j], acc[i][j]);
        }
    }

    // ---- epilogue: sum dist^2 * c_cycle^2 over this tile (with symmetry) ----
    float rk_r[8], fq_r[8], x_r[8], y_r[8];
    float rk_c[8], fq_c[8], x_c[8], y_c[8];
#pragma unroll
    for (int i = 0; i < 8; i++) {
        int r = ti * 128 + ty * 8 + i;
        rk_r[i] = g_rk[nm * K_ + r];
        fq_r[i] = g_fq[nm * K_ + r];
        x_r[i]  = g_fx[n * K_ + r];
        y_r[i]  = g_fy[n * K_ + r];
        int c = tj * 128 + tx * 8 + i;
        rk_c[i] = g_rk[nm * K_ + c];
        fq_c[i] = g_fq[nm * K_ + c];
        x_c[i]  = g_fx[n * K_ + c];
        y_c[i]  = g_fy[n * K_ + c];
    }
    bool diag = (ti == tj);
    float part = 0.f;
#pragma unroll
    for (int i = 0; i < 8; i++) {
#pragma unroll
        for (int j = 0; j < 8; j++) {
            float dx = x_r[i] - x_c[j];
            float dy = y_r[i] - y_c[j];
            float dist = fmaf(dx, dx, dy * dy);
            float gv = acc[i][j];
            float w1 = rk_r[i] * fq_c[j] * gv;
            float d2 = dist * dist;
            if (diag) {
                part = fmaf(d2, w1 * w1, part);
            } else {
                float w2 = rk_c[j] * fq_r[i] * gv;
                part = fmaf(d2, fmaf(w1, w1, w2 * w2), part);
            }
        }
    }
    red[tid] = part;
    __syncthreads();
    for (int o = 128; o > 0; o >>= 1) {
        if (tid < o) red[tid] += red[tid + o];
        __syncthreads();
    }
    if (tid == 0) g_partial[nm * NPAIR + pr] = red[0];
}

// ---------------- K6: final sqrt + mean ----------------
__global__ void k_final(float* __restrict__ out) {
    int t = threadIdx.x;           // 32 threads, one per nm
    float s = 0.f;
#pragma unroll
    for (int pr = 0; pr < NPAIR; pr++) s += g_partial[t * NPAIR + pr];
    float l = sqrtf(s);
#pragma unroll
    for (int o = 16; o > 0; o >>= 1) l += __shfl_xor_sync(0xffffffffu, l, o);
    if (t == 0) out[0] = l / (float)NM_;
}

// ---------------- launch ----------------
extern "C" void kernel_launch(void* const* d_in, const int* in_sizes, int n_in,
                              void* d_out, int out_size) {
    const float* pix  = (const float*)d_in[0];
    const float* mesh = (const float*)d_in[1];
    const void*  idx  = d_in[2];
    float* out = (float*)d_out;
    (void)in_sizes; (void)n_in; (void)out_size;

    k_detect<<<1, 256>>>((const int*)idx);
    k_sample<<<(N_ * K_ + 255) / 256, 256>>>(pix, idx);
    k_sim<<<dim3(NM_, NCH), 512>>>(mesh);
    k_rowmax<<<(NM_ * K_ + 255) / 256, 256>>>();
    k_rowsum<<<dim3(NM_, NCH), 512>>>();
    k_rowfin<<<(NM_ * K_ + 255) / 256, 256>>>();
    k_colstats<<<dim3(NM_, (V_ + 7) / 8), 256>>>();
    {
        size_t nvec = (size_t)NM_ * V_ * K_ / 4;
        k_etilde<<<(unsigned)((nvec + 255) / 256), 256>>>();
    }
    k_gemm<<<dim3(NM_, NPAIR), 256>>>();
    k_final<<<1, 32>>>(out);
}

// round 3
// speedup vs baseline: 1.0016x; 1.0016x over previous
#include <cuda_runtime.h>
#include <cstdint>
#include <cstddef>

// ---------------- problem constants ----------------
constexpr int N_  = 16;
constexpr int D_  = 16;
constexpr int S_  = 112;
constexpr int SS_ = S_ * S_;          // 12544
constexpr int M_  = 2;
constexpr int V_  = 7829;
constexpr int K_  = 512;
constexpr int NM_ = N_ * M_;          // 32
constexpr int NCH = 8;                // v-chunks for row passes
constexpr int VCH = (V_ + NCH - 1) / NCH;   // 979
constexpr int NPAIR = 10;             // lower-tri 128-tile pairs of a 4x4 grid
constexpr float TSCALE = 20.0f;       // 1/T
constexpr float BETA   = 42.0f;       // stability shift

// ---------------- static device scratch ----------------
__device__ float g_sim[(size_t)NM_ * V_ * K_];    // [nm][v][k]
__device__ float g_Et [(size_t)NM_ * V_ * K_];    // [nm][v][k]
__device__ float g_sampled[N_ * K_ * D_];
__device__ float g_fx[N_ * K_], g_fy[N_ * K_];
__device__ float g_rpmax[NM_ * NCH * K_];
__device__ float g_rpsum[NM_ * NCH * K_];
__device__ float g_tk[NM_ * K_];      // -20*rmax[k]
__device__ float g_rk[NM_ * K_];      // 1/rsum[k]
__device__ float g_fq[NM_ * K_];      // exp(20*rmax[k] - 2*BETA)
__device__ float g_sv[NM_ * V_];      // BETA - 10*cmax[v] - 0.5*ln(csum[v])
__device__ float g_partial[NM_ * NPAIR];
__device__ int   g_is64;

// ---------------- fast exp: pure FMA, ~1.3e-6 rel err ----------------
static __device__ __forceinline__ float fexp(float x) {
    float y = x * 1.4426950408889634f;           // x/ln2
    y = fminf(y, 126.0f);
    if (y < -126.0f) return 0.0f;
    float fl = floorf(y);
    float f  = y - fl;                            // [0,1)
    float p = 1.5252733804e-5f;
    p = fmaf(p, f, 1.5403530393e-4f);
    p = fmaf(p, f, 1.3333558146e-3f);
    p = fmaf(p, f, 9.6181291076e-3f);
    p = fmaf(p, f, 5.5504108664e-2f);
    p = fmaf(p, f, 2.4022650696e-1f);
    p = fmaf(p, f, 6.9314718056e-1f);
    p = fmaf(p, f, 1.0f);
    return __int_as_float(__float_as_int(p) + (((int)fl) << 23));
}

// ---------------- K0: detect int64 vs int32 indices ----------------
__global__ void k_detect(const int* __restrict__ w) {
    __shared__ int s_allzero;
    if (threadIdx.x == 0) s_allzero = 1;
    __syncthreads();
    int nz = 0;
    for (int i = threadIdx.x * 2 + 1; i < N_ * K_; i += blockDim.x * 2)
        if (w[i] != 0) nz = 1;
    if (nz) atomicAnd(&s_allzero, 0);
    __syncthreads();
    if (threadIdx.x == 0) g_is64 = s_allzero;   // all odd 32-bit words zero => int64
}

// ---------------- K1: gather + normalize sampled embeddings ----------------
__global__ void k_sample(const float* __restrict__ pix, const void* __restrict__ idxraw) {
    int t = blockIdx.x * blockDim.x + threadIdx.x;
    if (t >= N_ * K_) return;
    long long idx;
    if (g_is64) idx = ((const long long*)idxraw)[t];
    else        idx = (long long)((const int*)idxraw)[t];
    int n = t / K_;
    int p = (int)idx;
    g_fx[t] = (float)(p / S_);
    g_fy[t] = (float)(p % S_);
    const float* base = pix + (size_t)n * D_ * SS_ + p;
    float v[16]; float ss = 0.f;
#pragma unroll
    for (int d = 0; d < 16; d++) { v[d] = base[(size_t)d * SS_]; ss = fmaf(v[d], v[d], ss); }
    float inv = 1.0f / fmaxf(sqrtf(ss), 1e-6f);
#pragma unroll
    for (int d = 0; d < 16; d++) g_sampled[t * 16 + d] = v[d] * inv;
}

// ---------------- K2: sim[nm][v][k] + per-chunk row max (over v) ----------------
__global__ void __launch_bounds__(512) k_sim(const float* __restrict__ mesh) {
    int nm = blockIdx.x, ch = blockIdx.y;
    int k  = threadIdx.x;
    int n = nm / M_, m = nm % M_;
    float sk[16];
    const float* sp = &g_sampled[(n * K_ + k) * 16];
#pragma unroll
    for (int d = 0; d < 16; d++) sk[d] = sp[d];
    int v0 = ch * VCH;
    int v1 = min(v0 + VCH, V_);
    float mx = -1e30f;
    float* simbase = g_sim + (size_t)nm * V_ * K_;
    const float4* mb = (const float4*)(mesh + (size_t)m * V_ * D_);
    for (int v = v0; v < v1; v++) {
        float4 m0 = mb[v * 4 + 0], m1 = mb[v * 4 + 1];
        float4 m2 = mb[v * 4 + 2], m3 = mb[v * 4 + 3];
        float s;
        s =          sk[0]  * m0.x;     s = fmaf(sk[1],  m0.y, s);
        s = fmaf(sk[2],  m0.z, s);      s = fmaf(sk[3],  m0.w, s);
        s = fmaf(sk[4],  m1.x, s);      s = fmaf(sk[5],  m1.y, s);
        s = fmaf(sk[6],  m1.z, s);      s = fmaf(sk[7],  m1.w, s);
        s = fmaf(sk[8],  m2.x, s);      s = fmaf(sk[9],  m2.y, s);
        s = fmaf(sk[10], m2.z, s);      s = fmaf(sk[11], m2.w, s);
        s = fmaf(sk[12], m3.x, s);      s = fmaf(sk[13], m3.y, s);
        s = fmaf(sk[14], m3.z, s);      s = fmaf(sk[15], m3.w, s);
        simbase[(size_t)v * K_ + k] = s;
        mx = fmaxf(mx, s);
    }
    g_rpmax[(nm * NCH + ch) * K_ + k] = mx;
}

// ---------------- K2b: combine chunk maxes -> tk ----------------
__global__ void k_rowmax() {
    int t = blockIdx.x * blockDim.x + threadIdx.x;
    if (t >= NM_ * K_) return;
    int nm = t / K_, k = t % K_;
    float mx = -1e30f;
#pragma unroll
    for (int c = 0; c < NCH; c++) mx = fmaxf(mx, g_rpmax[(nm * NCH + c) * K_ + k]);
    g_tk[t] = -TSCALE * mx;
}

// ---------------- K2c: per-chunk row sums (needs final tk) ----------------
__global__ void __launch_bounds__(512) k_rowsum() {
    int nm = blockIdx.x, ch = blockIdx.y;
    int k  = threadIdx.x;
    float tk = g_tk[nm * K_ + k];
    int v0 = ch * VCH;
    int v1 = min(v0 + VCH, V_);
    const float* simbase = g_sim + (size_t)nm * V_ * K_;
    float s = 0.f;
    for (int v = v0; v < v1; v++)
        s += fexp(fmaf(TSCALE, simbase[(size_t)v * K_ + k], tk));
    g_rpsum[(nm * NCH + ch) * K_ + k] = s;
}

// ---------------- K2d: finalize rows -> rk, fq ----------------
__global__ void k_rowfin() {
    int t = blockIdx.x * blockDim.x + threadIdx.x;
    if (t >= NM_ * K_) return;
    int nm = t / K_, k = t % K_;
    float s = 0.f;
#pragma unroll
    for (int c = 0; c < NCH; c++) s += g_rpsum[(nm * NCH + c) * K_ + k];
    g_rk[t] = 1.0f / s;
    g_fq[t] = fexp(-g_tk[t] - 2.0f * BETA);
}

// ---------------- K3: column (over k) stats -> sv[v] ----------------
__global__ void k_colstats() {
    int nm = blockIdx.x;
    int v  = blockIdx.y * 8 + (threadIdx.x >> 5);
    int lane = threadIdx.x & 31;
    if (v >= V_) return;
    const float4* row = (const float4*)(g_sim + ((size_t)nm * V_ + v) * K_);
    float4 a = row[lane], b = row[lane + 32], c = row[lane + 64], d = row[lane + 96];
    float mx = fmaxf(fmaxf(fmaxf(a.x, a.y), fmaxf(a.z, a.w)),
               fmaxf(fmaxf(fmaxf(b.x, b.y), fmaxf(b.z, b.w)),
               fmaxf(fmaxf(fmaxf(c.x, c.y), fmaxf(c.z, c.w)),
                     fmaxf(fmaxf(d.x, d.y), fmaxf(d.z, d.w)))));
#pragma unroll
    for (int o = 16; o > 0; o >>= 1) mx = fmaxf(mx, __shfl_xor_sync(0xffffffffu, mx, o));
    float nmx = -TSCALE * mx;
    float s = fexp(fmaf(TSCALE, a.x, nmx)) + fexp(fmaf(TSCALE, a.y, nmx))
            + fexp(fmaf(TSCALE, a.z, nmx)) + fexp(fmaf(TSCALE, a.w, nmx))
            + fexp(fmaf(TSCALE, b.x, nmx)) + fexp(fmaf(TSCALE, b.y, nmx))
            + fexp(fmaf(TSCALE, b.z, nmx)) + fexp(fmaf(TSCALE, b.w, nmx))
            + fexp(fmaf(TSCALE, c.x, nmx)) + fexp(fmaf(TSCALE, c.y, nmx))
            + fexp(fmaf(TSCALE, c.z, nmx)) + fexp(fmaf(TSCALE, c.w, nmx))
            + fexp(fmaf(TSCALE, d.x, nmx)) + fexp(fmaf(TSCALE, d.y, nmx))
            + fexp(fmaf(TSCALE, d.z, nmx)) + fexp(fmaf(TSCALE, d.w, nmx));
#pragma unroll
    for (int o = 16; o > 0; o >>= 1) s += __shfl_xor_sync(0xffffffffu, s, o);
    if (lane == 0)
        g_sv[(size_t)nm * V_ + v] = BETA - 0.5f * TSCALE * mx - 0.5f * logf(s);
}

// ---------------- K4: Etilde = exp(20*sim + tk[k] + sv[v]) ----------------
__global__ void k_etilde() {
    size_t g = (size_t)blockIdx.x * blockDim.x + threadIdx.x;   // float4 id
    size_t e = g * 4;
    if (e >= (size_t)NM_ * V_ * K_) return;
    int    k  = (int)(e % K_);
    size_t vr = e / K_;
    int    nm = (int)(vr / V_);
    float sv = g_sv[vr];
    float4 tk4 = *(const float4*)&g_tk[nm * K_ + k];
    float4 s4  = *(const float4*)&g_sim[e];
    float4 o;
    o.x = fexp(fmaf(TSCALE, s4.x, tk4.x + sv));
    o.y = fexp(fmaf(TSCALE, s4.y, tk4.y + sv));
    o.z = fexp(fmaf(TSCALE, s4.z, tk4.z + sv));
    o.w = fexp(fmaf(TSCALE, s4.w, tk4.w + sv));
    *(float4*)&g_Et[e] = o;
}

// ---------------- K5: symmetric GEMM G = Et*Et^T per 128x128 pair + epilogue ----------------
__constant__ int c_ti[NPAIR] = {0,1,1,2,2,2,3,3,3,3};
__constant__ int c_tj[NPAIR] = {0,0,1,0,1,2,0,1,2,3};

__global__ void __launch_bounds__(256) k_gemm() {
    __shared__ float As[16][128];
    __shared__ float Bs[16][128];
    __shared__ float red[256];

    int nm = blockIdx.x, pr = blockIdx.y;
    int ti = c_ti[pr], tj = c_tj[pr];
    int n = nm / M_;
    int tid = threadIdx.x;
    int tx = tid & 15;           // col group (0..15)
    int ty = tid >> 4;           // row group (0..15)
    int r0 = tid >> 5;           // load row   (0..7)
    int c0 = (tid & 31) * 4;     // load col   (0..124)

    const float* EA = g_Et + (size_t)nm * V_ * K_ + ti * 128;
    const float* EB = g_Et + (size_t)nm * V_ * K_ + tj * 128;

    float acc[8][8];
#pragma unroll
    for (int i = 0; i < 8; i++)
#pragma unroll
        for (int j = 0; j < 8; j++) acc[i][j] = 0.f;

    const int NSTEP = (V_ + 15) / 16;
    for (int s = 0; s < NSTEP; s++) {
        int va = s * 16 + r0, vb = va + 8;
        float4 z = make_float4(0.f, 0.f, 0.f, 0.f);
        float4 a0 = (va < V_) ? *(const float4*)(EA + (size_t)va * K_ + c0) : z;
        float4 a1 = (vb < V_) ? *(const float4*)(EA + (size_t)vb * K_ + c0) : z;
        float4 b0 = (va < V_) ? *(const float4*)(EB + (size_t)va * K_ + c0) : z;
        float4 b1 = (vb < V_) ? *(const float4*)(EB + (size_t)vb * K_ + c0) : z;
        __syncthreads();
        *(float4*)&As[r0][c0]     = a0;
        *(float4*)&As[r0 + 8][c0] = a1;
        *(float4*)&Bs[r0][c0]     = b0;
        *(float4*)&Bs[r0 + 8][c0] = b1;
        __syncthreads();
#pragma unroll
        for (int kk = 0; kk < 16; kk++) {
            float ar[8], br[8];
            *(float4*)&ar[0] = *(const float4*)&As[kk][ty * 8];
            *(float4*)&ar[4] = *(const float4*)&As[kk][ty * 8 + 4];
            *(float4*)&br[0] = *(const float4*)&Bs[kk][tx * 8];
            *(float4*)&br[4] = *(const float4*)&Bs[kk][tx * 8 + 4];
#pragma unroll
            for (int i = 0; i < 8; i++)
#pragma unroll
                for (int j = 0; j < 8; j++)
                    acc[i][j] = fmaf(ar[i], br[j], acc[i][j]);
        }
    }

    // ---- epilogue: sum dist^2 * c_cycle^2 over this tile (with symmetry) ----
    float rk_r[8], fq_r[8], x_r[8], y_r[8];
    float rk_c[8], fq_c[8], x_c[8], y_c[8];
#pragma unroll
    for (int i = 0; i < 8; i++) {
        int r = ti * 128 + ty * 8 + i;
        rk_r[i] = g_rk[nm * K_ + r];
        fq_r[i] = g_fq[nm * K_ + r];
        x_r[i]  = g_fx[n * K_ + r];
        y_r[i]  = g_fy[n * K_ + r];
        int c = tj * 128 + tx * 8 + i;
        rk_c[i] = g_rk[nm * K_ + c];
        fq_c[i] = g_fq[nm * K_ + c];
        x_c[i]  = g_fx[n * K_ + c];
        y_c[i]  = g_fy[n * K_ + c];
    }
    bool diag = (ti == tj);
    float part = 0.f;
#pragma unroll
    for (int i = 0; i < 8; i++) {
#pragma unroll
        for (int j = 0; j < 8; j++) {
            float dx = x_r[i] - x_c[j];
            float dy = y_r[i] - y_c[j];
            float dist = fmaf(dx, dx, dy * dy);
            float gv = acc[i][j];
            float w1 = rk_r[i] * fq_c[j] * gv;
            float d2 = dist * dist;
            if (diag) {
                part = fmaf(d2, w1 * w1, part);
            } else {
                float w2 = rk_c[j] * fq_r[i] * gv;
                part = fmaf(d2, fmaf(w1, w1, w2 * w2), part);
            }
        }
    }
    red[tid] = part;
    __syncthreads();
    for (int o = 128; o > 0; o >>= 1) {
        if (tid < o) red[tid] += red[tid + o];
        __syncthreads();
    }
    if (tid == 0) g_partial[nm * NPAIR + pr] = red[0];
}

// ---------------- K6: final sqrt + mean ----------------
__global__ void k_final(float* __restrict__ out) {
    int t = threadIdx.x;           // 32 threads, one per nm
    float s = 0.f;
#pragma unroll
    for (int pr = 0; pr < NPAIR; pr++) s += g_partial[t * NPAIR + pr];
    float l = sqrtf(s);
#pragma unroll
    for (int o = 16; o > 0; o >>= 1) l += __shfl_xor_sync(0xffffffffu, l, o);
    if (t == 0) out[0] = l / (float)NM_;
}

// ---------------- launch ----------------
extern "C" void kernel_launch(void* const* d_in, const int* in_sizes, int n_in,
                              void* d_out, int out_size) {
    const float* pix  = (const float*)d_in[0];
    const float* mesh = (const float*)d_in[1];
    const void*  idx  = d_in[2];
    float* out = (float*)d_out;
    (void)in_sizes; (void)n_in; (void)out_size;

    k_detect<<<1, 256>>>((const int*)idx);
    k_sample<<<(N_ * K_ + 255) / 256, 256>>>(pix, idx);
    k_sim<<<dim3(NM_, NCH), 512>>>(mesh);
    k_rowmax<<<(NM_ * K_ + 255) / 256, 256>>>();
    k_rowsum<<<dim3(NM_, NCH), 512>>>();
    k_rowfin<<<(NM_ * K_ + 255) / 256, 256>>>();
    k_colstats<<<dim3(NM_, (V_ + 7) / 8), 256>>>();
    {
        size_t nvec = (size_t)NM_ * V_ * K_ / 4;
        k_etilde<<<(unsigned)((nvec + 255) / 256), 256>>>();
    }
    k_gemm<<<dim3(NM_, NPAIR), 256>>>();
    k_final<<<1, 32>>>(out);
}

// round 5
// speedup vs baseline: 2.4237x; 2.4198x over previous
#include <cuda_runtime.h>
#include <cstdint>
#include <cstddef>

// ---------------- problem constants ----------------
constexpr int N_  = 16;
constexpr int D_  = 16;
constexpr int S_  = 112;
constexpr int SS_ = S_ * S_;          // 12544
constexpr int M_  = 2;
constexpr int V_  = 7829;
constexpr int K_  = 512;
constexpr int NM_ = N_ * M_;          // 32
constexpr int NCH = 8;                // v-chunks for row passes
constexpr int VCH = (V_ + NCH - 1) / NCH;   // 979
constexpr int NPAIR = 10;             // lower-tri 128-tile pairs of a 4x4 grid
constexpr float TSCALE = 20.0f;       // 1/T
constexpr float BETA   = 42.0f;       // stability shift

// ---------------- static device scratch ----------------
__device__ float g_sim[(size_t)NM_ * V_ * K_];    // [nm][v][k]
__device__ float g_Et [(size_t)NM_ * V_ * K_];    // [nm][v][k], tf32-rounded
__device__ float g_sampled[N_ * K_ * D_];
__device__ float g_fx[N_ * K_], g_fy[N_ * K_];
__device__ float g_rpmax[NM_ * NCH * K_];
__device__ float g_rpsum[NM_ * NCH * K_];
__device__ float g_tk[NM_ * K_];      // -20*rmax[k]
__device__ float g_rk[NM_ * K_];      // 1/rsum[k]
__device__ float g_fq[NM_ * K_];      // exp(20*rmax[k] - 2*BETA)
__device__ float g_partial[NM_ * NPAIR];
__device__ int   g_is64;

// ---------------- fast exp: pure FMA, ~1.3e-6 rel err ----------------
static __device__ __forceinline__ float fexp(float x) {
    float y = x * 1.4426950408889634f;           // x/ln2
    y = fminf(y, 126.0f);
    if (y < -126.0f) return 0.0f;
    float fl = floorf(y);
    float f  = y - fl;                            // [0,1)
    float p = 1.5252733804e-5f;
    p = fmaf(p, f, 1.5403530393e-4f);
    p = fmaf(p, f, 1.3333558146e-3f);
    p = fmaf(p, f, 9.6181291076e-3f);
    p = fmaf(p, f, 5.5504108664e-2f);
    p = fmaf(p, f, 2.4022650696e-1f);
    p = fmaf(p, f, 6.9314718056e-1f);
    p = fmaf(p, f, 1.0f);
    return __int_as_float(__float_as_int(p) + (((int)fl) << 23));
}

static __device__ __forceinline__ float tf32r(float x) {
    uint32_t u;
    asm("cvt.rna.tf32.f32 %0, %1;" : "=r"(u) : "f"(x));
    return __uint_as_float(u);
}

// ---------------- K0: detect int64 vs int32 indices ----------------
__global__ void k_detect(const int* __restrict__ w) {
    __shared__ int s_allzero;
    if (threadIdx.x == 0) s_allzero = 1;
    __syncthreads();
    int nz = 0;
    for (int i = threadIdx.x * 2 + 1; i < N_ * K_; i += blockDim.x * 2)
        if (w[i] != 0) nz = 1;
    if (nz) atomicAnd(&s_allzero, 0);
    __syncthreads();
    if (threadIdx.x == 0) g_is64 = s_allzero;   // all odd 32-bit words zero => int64
}

// ---------------- K1: gather + normalize sampled embeddings ----------------
__global__ void k_sample(const float* __restrict__ pix, const void* __restrict__ idxraw) {
    int t = blockIdx.x * blockDim.x + threadIdx.x;
    if (t >= N_ * K_) return;
    long long idx;
    if (g_is64) idx = ((const long long*)idxraw)[t];
    else        idx = (long long)((const int*)idxraw)[t];
    int n = t / K_;
    int p = (int)idx;
    g_fx[t] = (float)(p / S_);
    g_fy[t] = (float)(p % S_);
    const float* base = pix + (size_t)n * D_ * SS_ + p;
    float v[16]; float ss = 0.f;
#pragma unroll
    for (int d = 0; d < 16; d++) { v[d] = base[(size_t)d * SS_]; ss = fmaf(v[d], v[d], ss); }
    float inv = 1.0f / fmaxf(sqrtf(ss), 1e-6f);
#pragma unroll
    for (int d = 0; d < 16; d++) g_sampled[t * 16 + d] = v[d] * inv;
}

// ---------------- K2: sim[nm][v][k] + per-chunk row max (over v) ----------------
__global__ void __launch_bounds__(512) k_sim(const float* __restrict__ mesh) {
    int nm = blockIdx.x, ch = blockIdx.y;
    int k  = threadIdx.x;
    int n = nm / M_, m = nm % M_;
    float sk[16];
    const float* sp = &g_sampled[(n * K_ + k) * 16];
#pragma unroll
    for (int d = 0; d < 16; d++) sk[d] = sp[d];
    int v0 = ch * VCH;
    int v1 = min(v0 + VCH, V_);
    float mx = -1e30f;
    float* simbase = g_sim + (size_t)nm * V_ * K_;
    const float4* mb = (const float4*)(mesh + (size_t)m * V_ * D_);
    for (int v = v0; v < v1; v++) {
        float4 m0 = mb[v * 4 + 0], m1 = mb[v * 4 + 1];
        float4 m2 = mb[v * 4 + 2], m3 = mb[v * 4 + 3];
        float s;
        s =          sk[0]  * m0.x;     s = fmaf(sk[1],  m0.y, s);
        s = fmaf(sk[2],  m0.z, s);      s = fmaf(sk[3],  m0.w, s);
        s = fmaf(sk[4],  m1.x, s);      s = fmaf(sk[5],  m1.y, s);
        s = fmaf(sk[6],  m1.z, s);      s = fmaf(sk[7],  m1.w, s);
        s = fmaf(sk[8],  m2.x, s);      s = fmaf(sk[9],  m2.y, s);
        s = fmaf(sk[10], m2.z, s);      s = fmaf(sk[11], m2.w, s);
        s = fmaf(sk[12], m3.x, s);      s = fmaf(sk[13], m3.y, s);
        s = fmaf(sk[14], m3.z, s);      s = fmaf(sk[15], m3.w, s);
        simbase[(size_t)v * K_ + k] = s;
        mx = fmaxf(mx, s);
    }
    g_rpmax[(nm * NCH + ch) * K_ + k] = mx;
}

// ---------------- K2b: combine chunk maxes -> tk ----------------
__global__ void k_rowmax() {
    int t = blockIdx.x * blockDim.x + threadIdx.x;
    if (t >= NM_ * K_) return;
    int nm = t / K_, k = t % K_;
    float mx = -1e30f;
#pragma unroll
    for (int c = 0; c < NCH; c++) mx = fmaxf(mx, g_rpmax[(nm * NCH + c) * K_ + k]);
    g_tk[t] = -TSCALE * mx;
}

// ---------------- K2c: per-chunk row sums (needs final tk) ----------------
__global__ void __launch_bounds__(512) k_rowsum() {
    int nm = blockIdx.x, ch = blockIdx.y;
    int k  = threadIdx.x;
    float tk = g_tk[nm * K_ + k];
    int v0 = ch * VCH;
    int v1 = min(v0 + VCH, V_);
    const float* simbase = g_sim + (size_t)nm * V_ * K_;
    float s = 0.f;
    for (int v = v0; v < v1; v++)
        s += fexp(fmaf(TSCALE, simbase[(size_t)v * K_ + k], tk));
    g_rpsum[(nm * NCH + ch) * K_ + k] = s;
}

// ---------------- K2d: finalize rows -> rk, fq ----------------
__global__ void k_rowfin() {
    int t = blockIdx.x * blockDim.x + threadIdx.x;
    if (t >= NM_ * K_) return;
    float s = 0.f;
    int nm = t / K_, k = t % K_;
#pragma unroll
    for (int c = 0; c < NCH; c++) s += g_rpsum[(nm * NCH + c) * K_ + k];
    g_rk[t] = 1.0f / s;
    g_fq[t] = fexp(-g_tk[t] - 2.0f * BETA);
}

// ---------------- K3: fused column stats + Etilde (tf32-rounded) ----------------
__global__ void __launch_bounds__(256) k_colet() {
    int nm = blockIdx.x;
    int v  = blockIdx.y * 8 + (threadIdx.x >> 5);
    int lane = threadIdx.x & 31;
    if (v >= V_) return;
    const float4* row = (const float4*)(g_sim + ((size_t)nm * V_ + v) * K_);
    float4 a = row[lane], b = row[lane + 32], c = row[lane + 64], d = row[lane + 96];
    float mx = fmaxf(fmaxf(fmaxf(a.x, a.y), fmaxf(a.z, a.w)),
               fmaxf(fmaxf(fmaxf(b.x, b.y), fmaxf(b.z, b.w)),
               fmaxf(fmaxf(fmaxf(c.x, c.y), fmaxf(c.z, c.w)),
                     fmaxf(fmaxf(d.x, d.y), fmaxf(d.z, d.w)))));
#pragma unroll
    for (int o = 16; o > 0; o >>= 1) mx = fmaxf(mx, __shfl_xor_sync(0xffffffffu, mx, o));
    float nmx = -TSCALE * mx;
    float s = fexp(fmaf(TSCALE, a.x, nmx)) + fexp(fmaf(TSCALE, a.y, nmx))
            + fexp(fmaf(TSCALE, a.z, nmx)) + fexp(fmaf(TSCALE, a.w, nmx))
            + fexp(fmaf(TSCALE, b.x, nmx)) + fexp(fmaf(TSCALE, b.y, nmx))
            + fexp(fmaf(TSCALE, b.z, nmx)) + fexp(fmaf(TSCALE, b.w, nmx))
            + fexp(fmaf(TSCALE, c.x, nmx)) + fexp(fmaf(TSCALE, c.y, nmx))
            + fexp(fmaf(TSCALE, c.z, nmx)) + fexp(fmaf(TSCALE, c.w, nmx))
            + fexp(fmaf(TSCALE, d.x, nmx)) + fexp(fmaf(TSCALE, d.y, nmx))
            + fexp(fmaf(TSCALE, d.z, nmx)) + fexp(fmaf(TSCALE, d.w, nmx));
#pragma unroll
    for (int o = 16; o > 0; o >>= 1) s += __shfl_xor_sync(0xffffffffu, s, o);
    float sv = BETA - 0.5f * TSCALE * mx - 0.5f * logf(s);   // all lanes have it

    const float4* tkb = (const float4*)(g_tk + nm * K_);
    float4 t0 = tkb[lane], t1 = tkb[lane + 32], t2 = tkb[lane + 64], t3 = tkb[lane + 96];
    float4* out = (float4*)(g_Et + ((size_t)nm * V_ + v) * K_);
    float4 o;
    o.x = tf32r(fexp(fmaf(TSCALE, a.x, t0.x + sv)));
    o.y = tf32r(fexp(fmaf(TSCALE, a.y, t0.y + sv)));
    o.z = tf32r(fexp(fmaf(TSCALE, a.z, t0.z + sv)));
    o.w = tf32r(fexp(fmaf(TSCALE, a.w, t0.w + sv)));
    out[lane] = o;
    o.x = tf32r(fexp(fmaf(TSCALE, b.x, t1.x + sv)));
    o.y = tf32r(fexp(fmaf(TSCALE, b.y, t1.y + sv)));
    o.z = tf32r(fexp(fmaf(TSCALE, b.z, t1.z + sv)));
    o.w = tf32r(fexp(fmaf(TSCALE, b.w, t1.w + sv)));
    out[lane + 32] = o;
    o.x = tf32r(fexp(fmaf(TSCALE, c.x, t2.x + sv)));
    o.y = tf32r(fexp(fmaf(TSCALE, c.y, t2.y + sv)));
    o.z = tf32r(fexp(fmaf(TSCALE, c.z, t2.z + sv)));
    o.w = tf32r(fexp(fmaf(TSCALE, c.w, t2.w + sv)));
    out[lane + 64] = o;
    o.x = tf32r(fexp(fmaf(TSCALE, d.x, t3.x + sv)));
    o.y = tf32r(fexp(fmaf(TSCALE, d.y, t3.y + sv)));
    o.z = tf32r(fexp(fmaf(TSCALE, d.z, t3.z + sv)));
    o.w = tf32r(fexp(fmaf(TSCALE, d.w, t3.w + sv)));
    out[lane + 96] = o;
}

// ---------------- K5: tf32 tensor-core symmetric GEMM + fused epilogue ----------------
__constant__ int c_ti[NPAIR] = {0,1,1,2,2,2,3,3,3,3};
__constant__ int c_tj[NPAIR] = {0,0,1,0,1,2,0,1,2,3};

// smem stride 136 floats: bank index of (kv, col) = (kv*8 + col) mod 32 -> conflict-free
__global__ void __launch_bounds__(256) k_gemm() {
    __shared__ float As[16][136];
    __shared__ float Bs[16][136];
    __shared__ float sRow[4][128];   // rk, fq, x, y
    __shared__ float sCol[4][128];
    __shared__ float red[256];

    int nm = blockIdx.x, pr = blockIdx.y;
    int ti = c_ti[pr], tj = c_tj[pr];
    bool diag = (ti == tj);
    int n = nm / M_;
    int tid  = threadIdx.x;
    int lane = tid & 31;
    int w    = tid >> 5;
    int wr   = w >> 2;        // 0..1  -> warp rows at wr*64
    int wc   = w & 3;         // 0..3  -> warp cols at wc*32

    if (tid < 128) {
        int r = ti * 128 + tid;
        sRow[0][tid] = g_rk[nm * K_ + r];
        sRow[1][tid] = g_fq[nm * K_ + r];
        sRow[2][tid] = g_fx[n * K_ + r];
        sRow[3][tid] = g_fy[n * K_ + r];
    } else {
        int t = tid - 128;
        int cc = tj * 128 + t;
        sCol[0][t] = g_rk[nm * K_ + cc];
        sCol[1][t] = g_fq[nm * K_ + cc];
        sCol[2][t] = g_fx[n * K_ + cc];
        sCol[3][t] = g_fy[n * K_ + cc];
    }

    const float* EA = g_Et + (size_t)nm * V_ * K_ + ti * 128;
    const float* EB = g_Et + (size_t)nm * V_ * K_ + tj * 128;

    float acc[16][4];
#pragma unroll
    for (int i = 0; i < 16; i++)
#pragma unroll
        for (int j = 0; j < 4; j++) acc[i][j] = 0.f;

    int r0 = tid >> 5;            // 0..7
    int c0 = (tid & 31) * 4;      // 0..124

    const int NSTEP = (V_ + 15) / 16;   // 490
    float4 pa0, pa1, pb0, pb1;
    {
        int va = r0, vb = r0 + 8;
        float4 z = make_float4(0.f, 0.f, 0.f, 0.f);
        pa0 = (va < V_) ? *(const float4*)(EA + (size_t)va * K_ + c0) : z;
        pa1 = (vb < V_) ? *(const float4*)(EA + (size_t)vb * K_ + c0) : z;
        if (!diag) {
            pb0 = (va < V_) ? *(const float4*)(EB + (size_t)va * K_ + c0) : z;
            pb1 = (vb < V_) ? *(const float4*)(EB + (size_t)vb * K_ + c0) : z;
        }
    }

    int gid = lane >> 2;     // 0..7
    int tig = lane & 3;      // 0..3
    int arow = wr * 64 + gid;
    int bcol = wc * 32 + gid;

    for (int s = 0; s < NSTEP; s++) {
        __syncthreads();
        *(float4*)&As[r0][c0]     = pa0;
        *(float4*)&As[r0 + 8][c0] = pa1;
        if (!diag) {
            *(float4*)&Bs[r0][c0]     = pb0;
            *(float4*)&Bs[r0 + 8][c0] = pb1;
        }
        __syncthreads();
        if (s + 1 < NSTEP) {
            int va = (s + 1) * 16 + r0, vb = va + 8;
            float4 z = make_float4(0.f, 0.f, 0.f, 0.f);
            pa0 = (va < V_) ? *(const float4*)(EA + (size_t)va * K_ + c0) : z;
            pa1 = (vb < V_) ? *(const float4*)(EA + (size_t)vb * K_ + c0) : z;
            if (!diag) {
                pb0 = (va < V_) ? *(const float4*)(EB + (size_t)va * K_ + c0) : z;
                pb1 = (vb < V_) ? *(const float4*)(EB + (size_t)vb * K_ + c0) : z;
            }
        }
        float (*BsP)[136] = diag ? As : Bs;
#pragma unroll
        for (int h = 0; h < 2; h++) {
            int kv0 = h * 8 + tig;
            uint32_t afr[4][4], bfr[4][2];
#pragma unroll
            for (int mt = 0; mt < 4; mt++) {
                afr[mt][0] = __float_as_uint(As[kv0    ][arow + mt * 16]);
                afr[mt][1] = __float_as_uint(As[kv0    ][arow + mt * 16 + 8]);
                afr[mt][2] = __float_as_uint(As[kv0 + 4][arow + mt * 16]);
                afr[mt][3] = __float_as_uint(As[kv0 + 4][arow + mt * 16 + 8]);
            }
#pragma unroll
            for (int nt = 0; nt < 4; nt++) {
                bfr[nt][0] = __float_as_uint(BsP[kv0    ][bcol + nt * 8]);
                bfr[nt][1] = __float_as_uint(BsP[kv0 + 4][bcol + nt * 8]);
            }
#pragma unroll
            for (int mt = 0; mt < 4; mt++)
#pragma unroll
                for (int nt = 0; nt < 4; nt++) {
                    float* dd = acc[mt * 4 + nt];
                    asm volatile(
                        "mma.sync.aligned.m16n8k8.row.col.f32.tf32.tf32.f32 "
                        "{%0,%1,%2,%3}, {%4,%5,%6,%7}, {%8,%9}, {%0,%1,%2,%3};"
                        : "+f"(dd[0]), "+f"(dd[1]), "+f"(dd[2]), "+f"(dd[3])
                        : "r"(afr[mt][0]), "r"(afr[mt][1]), "r"(afr[mt][2]), "r"(afr[mt][3]),
                          "r"(bfr[nt][0]), "r"(bfr[nt][1]));
                }
        }
    }

    // ---- epilogue: sum dist^2 * c_cycle^2 (with symmetry) ----
    float part = 0.f;
#pragma unroll
    for (int mt = 0; mt < 4; mt++)
#pragma unroll
        for (int nt = 0; nt < 4; nt++)
#pragma unroll
            for (int rg = 0; rg < 4; rg++) {
                int r = wr * 64 + mt * 16 + gid + ((rg >= 2) ? 8 : 0);
                int c = wc * 32 + nt * 8 + tig * 2 + (rg & 1);
                float dx = sRow[2][r] - sCol[2][c];
                float dy = sRow[3][r] - sCol[3][c];
                float dist = fmaf(dx, dx, dy * dy);
                float gv = acc[mt * 4 + nt][rg];
                float w1 = sRow[0][r] * sCol[1][c] * gv;
                float d2 = dist * dist;
                if (diag) {
                    part = fmaf(d2, w1 * w1, part);
                } else {
                    float w2 = sCol[0][c] * sRow[1][r] * gv;
                    part = fmaf(d2, fmaf(w1, w1, w2 * w2), part);
                }
            }
    red[tid] = part;
    __syncthreads();
    for (int o = 128; o > 0; o >>= 1) {
        if (tid < o) red[tid] += red[tid + o];
        __syncthreads();
    }
    if (tid == 0) g_partial[nm * NPAIR + pr] = red[0];
}

// ---------------- K6: final sqrt + mean ----------------
__global__ void k_final(float* __restrict__ out) {
    int t = threadIdx.x;           // 32 threads, one per nm
    float s = 0.f;
#pragma unroll
    for (int pr = 0; pr < NPAIR; pr++) s += g_partial[t * NPAIR + pr];
    float l = sqrtf(s);
#pragma unroll
    for (int o = 16; o > 0; o >>= 1) l += __shfl_xor_sync(0xffffffffu, l, o);
    if (t == 0) out[0] = l / (float)NM_;
}

// ---------------- launch ----------------
extern "C" void kernel_launch(void* const* d_in, const int* in_sizes, int n_in,
                              void* d_out, int out_size) {
    const float* pix  = (const float*)d_in[0];
    const float* mesh = (const float*)d_in[1];
    const void*  idx  = d_in[2];
    float* out = (float*)d_out;
    (void)in_sizes; (void)n_in; (void)out_size;

    k_detect<<<1, 256>>>((const int*)idx);
    k_sample<<<(N_ * K_ + 255) / 256, 256>>>(pix, idx);
    k_sim<<<dim3(NM_, NCH), 512>>>(mesh);
    k_rowmax<<<(NM_ * K_ + 255) / 256, 256>>>();
    k_rowsum<<<dim3(NM_, NCH), 512>>>();
    k_rowfin<<<(NM_ * K_ + 255) / 256, 256>>>();
    k_colet<<<dim3(NM_, (V_ + 7) / 8), 256>>>();
    k_gemm<<<dim3(NM_, NPAIR), 256>>>();
    k_final<<<1, 32>>>(out);
}

// round 6
// speedup vs baseline: 2.6811x; 1.1062x over previous
#include <cuda_runtime.h>
#include <cuda_bf16.h>
#include <cstdint>
#include <cstddef>

// ---------------- problem constants ----------------
constexpr int N_  = 16;
constexpr int D_  = 16;
constexpr int S_  = 112;
constexpr int SS_ = S_ * S_;          // 12544
constexpr int M_  = 2;
constexpr int V_  = 7829;
constexpr int K_  = 512;
constexpr int NM_ = N_ * M_;          // 32
constexpr int VP_ = (V_ + 1) / 2;     // 3915 v-pairs (last pair half-empty)
constexpr int NCH = 8;                // v-chunks for row passes
constexpr int VCH = (V_ + NCH - 1) / NCH;   // 979
constexpr int NPAIR = 10;             // lower-tri 128-tile pairs of a 4x4 grid
constexpr float TSCALE = 20.0f;       // 1/T
constexpr float BETA   = 42.0f;       // stability shift

// ---------------- static device scratch ----------------
__device__ float    g_sim[(size_t)NM_ * V_ * K_];   // [nm][v][k]
__device__ uint32_t g_Etp[(size_t)NM_ * VP_ * K_];  // [nm][vp][k] packed bf16x2 {v even, v odd}
__device__ float g_sampled[N_ * K_ * D_];
__device__ float g_fx[N_ * K_], g_fy[N_ * K_];
__device__ float g_rpmax[NM_ * NCH * K_];
__device__ float g_rpsum[NM_ * NCH * K_];
__device__ float g_tk[NM_ * K_];      // -20*rmax[k]
__device__ float g_rk[NM_ * K_];      // 1/rsum[k]
__device__ float g_fq[NM_ * K_];      // exp(20*rmax[k] - 2*BETA)
__device__ float g_partial[NM_ * NPAIR];
__device__ int   g_is64;

// ---------------- fast exp: pure FMA, ~1.3e-6 rel err ----------------
static __device__ __forceinline__ float fexp(float x) {
    float y = x * 1.4426950408889634f;           // x/ln2
    y = fminf(y, 126.0f);
    if (y < -126.0f) return 0.0f;
    float fl = floorf(y);
    float f  = y - fl;                            // [0,1)
    float p = 1.5252733804e-5f;
    p = fmaf(p, f, 1.5403530393e-4f);
    p = fmaf(p, f, 1.3333558146e-3f);
    p = fmaf(p, f, 9.6181291076e-3f);
    p = fmaf(p, f, 5.5504108664e-2f);
    p = fmaf(p, f, 2.4022650696e-1f);
    p = fmaf(p, f, 6.9314718056e-1f);
    p = fmaf(p, f, 1.0f);
    return __int_as_float(__float_as_int(p) + (((int)fl) << 23));
}

static __device__ __forceinline__ uint32_t bf16pair(float lo, float hi) {
    __nv_bfloat162 p = __floats2bfloat162_rn(lo, hi);   // .x = lo (low 16 bits)
    return *reinterpret_cast<uint32_t*>(&p);
}

// ---------------- K0: detect int64 vs int32 indices ----------------
__global__ void k_detect(const int* __restrict__ w) {
    __shared__ int s_allzero;
    if (threadIdx.x == 0) s_allzero = 1;
    __syncthreads();
    int nz = 0;
    for (int i = threadIdx.x * 2 + 1; i < N_ * K_; i += blockDim.x * 2)
        if (w[i] != 0) nz = 1;
    if (nz) atomicAnd(&s_allzero, 0);
    __syncthreads();
    if (threadIdx.x == 0) g_is64 = s_allzero;   // all odd 32-bit words zero => int64
}

// ---------------- K1: gather + normalize sampled embeddings ----------------
__global__ void k_sample(const float* __restrict__ pix, const void* __restrict__ idxraw) {
    int t = blockIdx.x * blockDim.x + threadIdx.x;
    if (t >= N_ * K_) return;
    long long idx;
    if (g_is64) idx = ((const long long*)idxraw)[t];
    else        idx = (long long)((const int*)idxraw)[t];
    int n = t / K_;
    int p = (int)idx;
    g_fx[t] = (float)(p / S_);
    g_fy[t] = (float)(p % S_);
    const float* base = pix + (size_t)n * D_ * SS_ + p;
    float v[16]; float ss = 0.f;
#pragma unroll
    for (int d = 0; d < 16; d++) { v[d] = base[(size_t)d * SS_]; ss = fmaf(v[d], v[d], ss); }
    float inv = 1.0f / fmaxf(sqrtf(ss), 1e-6f);
#pragma unroll
    for (int d = 0; d < 16; d++) g_sampled[t * 16 + d] = v[d] * inv;
}

// ---------------- K2: sim[nm][v][k] + per-chunk row max (over v) ----------------
__global__ void __launch_bounds__(512) k_sim(const float* __restrict__ mesh) {
    int nm = blockIdx.x, ch = blockIdx.y;
    int k  = threadIdx.x;
    int n = nm / M_, m = nm % M_;
    float sk[16];
    const float* sp = &g_sampled[(n * K_ + k) * 16];
#pragma unroll
    for (int d = 0; d < 16; d++) sk[d] = sp[d];
    int v0 = ch * VCH;
    int v1 = min(v0 + VCH, V_);
    float mx = -1e30f;
    float* simbase = g_sim + (size_t)nm * V_ * K_;
    const float4* mb = (const float4*)(mesh + (size_t)m * V_ * D_);
    for (int v = v0; v < v1; v++) {
        float4 m0 = mb[v * 4 + 0], m1 = mb[v * 4 + 1];
        float4 m2 = mb[v * 4 + 2], m3 = mb[v * 4 + 3];
        float s;
        s =          sk[0]  * m0.x;     s = fmaf(sk[1],  m0.y, s);
        s = fmaf(sk[2],  m0.z, s);      s = fmaf(sk[3],  m0.w, s);
        s = fmaf(sk[4],  m1.x, s);      s = fmaf(sk[5],  m1.y, s);
        s = fmaf(sk[6],  m1.z, s);      s = fmaf(sk[7],  m1.w, s);
        s = fmaf(sk[8],  m2.x, s);      s = fmaf(sk[9],  m2.y, s);
        s = fmaf(sk[10], m2.z, s);      s = fmaf(sk[11], m2.w, s);
        s = fmaf(sk[12], m3.x, s);      s = fmaf(sk[13], m3.y, s);
        s = fmaf(sk[14], m3.z, s);      s = fmaf(sk[15], m3.w, s);
        simbase[(size_t)v * K_ + k] = s;
        mx = fmaxf(mx, s);
    }
    g_rpmax[(nm * NCH + ch) * K_ + k] = mx;
}

// ---------------- K2b: combine chunk maxes -> tk ----------------
__global__ void k_rowmax() {
    int t = blockIdx.x * blockDim.x + threadIdx.x;
    if (t >= NM_ * K_) return;
    int nm = t / K_, k = t % K_;
    float mx = -1e30f;
#pragma unroll
    for (int c = 0; c < NCH; c++) mx = fmaxf(mx, g_rpmax[(nm * NCH + c) * K_ + k]);
    g_tk[t] = -TSCALE * mx;
}

// ---------------- K2c: per-chunk row sums (needs final tk) ----------------
__global__ void __launch_bounds__(512) k_rowsum() {
    int nm = blockIdx.x, ch = blockIdx.y;
    int k  = threadIdx.x;
    float tk = g_tk[nm * K_ + k];
    int v0 = ch * VCH;
    int v1 = min(v0 + VCH, V_);
    const float* simbase = g_sim + (size_t)nm * V_ * K_;
    float s = 0.f;
    for (int v = v0; v < v1; v++)
        s += fexp(fmaf(TSCALE, simbase[(size_t)v * K_ + k], tk));
    g_rpsum[(nm * NCH + ch) * K_ + k] = s;
}

// ---------------- K2d: finalize rows -> rk, fq ----------------
__global__ void k_rowfin() {
    int t = blockIdx.x * blockDim.x + threadIdx.x;
    if (t >= NM_ * K_) return;
    float s = 0.f;
    int nm = t / K_, k = t % K_;
#pragma unroll
    for (int c = 0; c < NCH; c++) s += g_rpsum[(nm * NCH + c) * K_ + k];
    g_rk[t] = 1.0f / s;
    g_fq[t] = fexp(-g_tk[t] - 2.0f * BETA);
}

// ---------------- K3: fused column stats + Etilde, packed bf16x2 pair output ----------------
// One warp per v-PAIR: compute col stats for rows v0=2vp and v1=2vp+1, then write
// packed word[(nm*VP+vp)*K + k] = {bf16(Et[v0][k]), bf16(Et[v1][k])}.
__global__ void __launch_bounds__(256) k_colet() {
    int nm = blockIdx.x;
    int vp = blockIdx.y * 8 + (threadIdx.x >> 5);
    int lane = threadIdx.x & 31;
    if (vp >= VP_) return;
    int v0 = vp * 2;
    bool has1 = (v0 + 1 < V_);

    const float4* rowA = (const float4*)(g_sim + ((size_t)nm * V_ + v0) * K_);
    const float4* rowB = (const float4*)(g_sim + ((size_t)nm * V_ + min(v0 + 1, V_ - 1)) * K_);
    float4 a0 = rowA[lane], a1 = rowA[lane + 32], a2 = rowA[lane + 64], a3 = rowA[lane + 96];
    float4 b0 = rowB[lane], b1 = rowB[lane + 32], b2 = rowB[lane + 64], b3 = rowB[lane + 96];

    // --- stats row A ---
    float mxa = fmaxf(fmaxf(fmaxf(a0.x, a0.y), fmaxf(a0.z, a0.w)),
                fmaxf(fmaxf(fmaxf(a1.x, a1.y), fmaxf(a1.z, a1.w)),
                fmaxf(fmaxf(fmaxf(a2.x, a2.y), fmaxf(a2.z, a2.w)),
                      fmaxf(fmaxf(a3.x, a3.y), fmaxf(a3.z, a3.w)))));
#pragma unroll
    for (int o = 16; o > 0; o >>= 1) mxa = fmaxf(mxa, __shfl_xor_sync(0xffffffffu, mxa, o));
    float nma = -TSCALE * mxa;
    float sa = fexp(fmaf(TSCALE, a0.x, nma)) + fexp(fmaf(TSCALE, a0.y, nma))
             + fexp(fmaf(TSCALE, a0.z, nma)) + fexp(fmaf(TSCALE, a0.w, nma))
             + fexp(fmaf(TSCALE, a1.x, nma)) + fexp(fmaf(TSCALE, a1.y, nma))
             + fexp(fmaf(TSCALE, a1.z, nma)) + fexp(fmaf(TSCALE, a1.w, nma))
             + fexp(fmaf(TSCALE, a2.x, nma)) + fexp(fmaf(TSCALE, a2.y, nma))
             + fexp(fmaf(TSCALE, a2.z, nma)) + fexp(fmaf(TSCALE, a2.w, nma))
             + fexp(fmaf(TSCALE, a3.x, nma)) + fexp(fmaf(TSCALE, a3.y, nma))
             + fexp(fmaf(TSCALE, a3.z, nma)) + fexp(fmaf(TSCALE, a3.w, nma));
#pragma unroll
    for (int o = 16; o > 0; o >>= 1) sa += __shfl_xor_sync(0xffffffffu, sa, o);
    float svA = BETA - 0.5f * TSCALE * mxa - 0.5f * logf(sa);

    // --- stats row B ---
    float mxb = fmaxf(fmaxf(fmaxf(b0.x, b0.y), fmaxf(b0.z, b0.w)),
                fmaxf(fmaxf(fmaxf(b1.x, b1.y), fmaxf(b1.z, b1.w)),
                fmaxf(fmaxf(fmaxf(b2.x, b2.y), fmaxf(b2.z, b2.w)),
                      fmaxf(fmaxf(b3.x, b3.y), fmaxf(b3.z, b3.w)))));
#pragma unroll
    for (int o = 16; o > 0; o >>= 1) mxb = fmaxf(mxb, __shfl_xor_sync(0xffffffffu, mxb, o));
    float nmb = -TSCALE * mxb;
    float sb = fexp(fmaf(TSCALE, b0.x, nmb)) + fexp(fmaf(TSCALE, b0.y, nmb))
             + fexp(fmaf(TSCALE, b0.z, nmb)) + fexp(fmaf(TSCALE, b0.w, nmb))
             + fexp(fmaf(TSCALE, b1.x, nmb)) + fexp(fmaf(TSCALE, b1.y, nmb))
             + fexp(fmaf(TSCALE, b1.z, nmb)) + fexp(fmaf(TSCALE, b1.w, nmb))
             + fexp(fmaf(TSCALE, b2.x, nmb)) + fexp(fmaf(TSCALE, b2.y, nmb))
             + fexp(fmaf(TSCALE, b2.z, nmb)) + fexp(fmaf(TSCALE, b2.w, nmb))
             + fexp(fmaf(TSCALE, b3.x, nmb)) + fexp(fmaf(TSCALE, b3.y, nmb))
             + fexp(fmaf(TSCALE, b3.z, nmb)) + fexp(fmaf(TSCALE, b3.w, nmb));
#pragma unroll
    for (int o = 16; o > 0; o >>= 1) sb += __shfl_xor_sync(0xffffffffu, sb, o);
    float svB = BETA - 0.5f * TSCALE * mxb - 0.5f * logf(sb);

    const float4* tkb = (const float4*)(g_tk + nm * K_);
    float4 t0 = tkb[lane], t1 = tkb[lane + 32], t2 = tkb[lane + 64], t3 = tkb[lane + 96];
    uint32_t* out = g_Etp + ((size_t)nm * VP_ + vp) * K_;
    uint4 o4;

    #define PK(ta, sa4, sb4) bf16pair( \
        fexp(fmaf(TSCALE, sa4, (ta) + svA)), \
        has1 ? fexp(fmaf(TSCALE, sb4, (ta) + svB)) : 0.0f)

    o4.x = PK(t0.x, a0.x, b0.x); o4.y = PK(t0.y, a0.y, b0.y);
    o4.z = PK(t0.z, a0.z, b0.z); o4.w = PK(t0.w, a0.w, b0.w);
    *(uint4*)&out[lane * 4] = o4;
    o4.x = PK(t1.x, a1.x, b1.x); o4.y = PK(t1.y, a1.y, b1.y);
    o4.z = PK(t1.z, a1.z, b1.z); o4.w = PK(t1.w, a1.w, b1.w);
    *(uint4*)&out[(lane + 32) * 4] = o4;
    o4.x = PK(t2.x, a2.x, b2.x); o4.y = PK(t2.y, a2.y, b2.y);
    o4.z = PK(t2.z, a2.z, b2.z); o4.w = PK(t2.w, a2.w, b2.w);
    *(uint4*)&out[(lane + 64) * 4] = o4;
    o4.x = PK(t3.x, a3.x, b3.x); o4.y = PK(t3.y, a3.y, b3.y);
    o4.z = PK(t3.z, a3.z, b3.z); o4.w = PK(t3.w, a3.w, b3.w);
    *(uint4*)&out[(lane + 96) * 4] = o4;
    #undef PK
}

// ---------------- K5: bf16 m16n8k16 symmetric GEMM + fused epilogue ----------------
__constant__ int c_ti[NPAIR] = {0,1,1,2,2,2,3,3,3,3};
__constant__ int c_tj[NPAIR] = {0,0,1,0,1,2,0,1,2,3};

// smem stride 136 words: fragment LDS banks = (8*tig + gid) mod 32 -> conflict-free
__global__ void __launch_bounds__(256) k_gemm() {
    __shared__ uint32_t As[8][136];
    __shared__ uint32_t Bs[8][136];
    __shared__ float sRow[4][128];   // rk, fq, x, y
    __shared__ float sCol[4][128];
    __shared__ float red[256];

    int nm = blockIdx.x, pr = blockIdx.y;
    int ti = c_ti[pr], tj = c_tj[pr];
    bool diag = (ti == tj);
    int n = nm / M_;
    int tid  = threadIdx.x;
    int lane = tid & 31;
    int w    = tid >> 5;
    int wr   = w >> 2;        // 0..1  -> warp rows at wr*64
    int wc   = w & 3;         // 0..3  -> warp cols at wc*32

    if (tid < 128) {
        int r = ti * 128 + tid;
        sRow[0][tid] = g_rk[nm * K_ + r];
        sRow[1][tid] = g_fq[nm * K_ + r];
        sRow[2][tid] = g_fx[n * K_ + r];
        sRow[3][tid] = g_fy[n * K_ + r];
    } else {
        int t = tid - 128;
        int cc = tj * 128 + t;
        sCol[0][t] = g_rk[nm * K_ + cc];
        sCol[1][t] = g_fq[nm * K_ + cc];
        sCol[2][t] = g_fx[n * K_ + cc];
        sCol[3][t] = g_fy[n * K_ + cc];
    }

    const uint32_t* EA = g_Etp + (size_t)nm * VP_ * K_ + ti * 128;
    const uint32_t* EB = g_Etp + (size_t)nm * VP_ * K_ + tj * 128;

    float acc[16][4];
#pragma unroll
    for (int i = 0; i < 16; i++)
#pragma unroll
        for (int j = 0; j < 4; j++) acc[i][j] = 0.f;

    int r0 = tid >> 5;            // 0..7 (one vp-row per warp when loading)
    int c0 = (tid & 31) * 4;      // 0..124

    const int NSTEP = (VP_ + 7) / 8;   // 490
    uint4 pa, pb;
    {
        int vp = r0;
        uint4 z = make_uint4(0u, 0u, 0u, 0u);
        pa = (vp < VP_) ? *(const uint4*)(EA + (size_t)vp * K_ + c0) : z;
        if (!diag) pb = (vp < VP_) ? *(const uint4*)(EB + (size_t)vp * K_ + c0) : z;
    }

    int gid = lane >> 2;     // 0..7
    int tig = lane & 3;      // 0..3
    int arow = wr * 64 + gid;
    int bcol = wc * 32 + gid;

    for (int s = 0; s < NSTEP; s++) {
        __syncthreads();
        *(uint4*)&As[r0][c0] = pa;
        if (!diag) *(uint4*)&Bs[r0][c0] = pb;
        __syncthreads();
        if (s + 1 < NSTEP) {
            int vp = (s + 1) * 8 + r0;
            uint4 z = make_uint4(0u, 0u, 0u, 0u);
            pa = (vp < VP_) ? *(const uint4*)(EA + (size_t)vp * K_ + c0) : z;
            if (!diag) pb = (vp < VP_) ? *(const uint4*)(EB + (size_t)vp * K_ + c0) : z;
        }
        uint32_t (*BsP)[136] = diag ? As : Bs;
        uint32_t afr[4][4], bfr[4][2];
#pragma unroll
        for (int mt = 0; mt < 4; mt++) {
            afr[mt][0] = As[tig    ][arow + mt * 16];
            afr[mt][1] = As[tig    ][arow + mt * 16 + 8];
            afr[mt][2] = As[tig + 4][arow + mt * 16];
            afr[mt][3] = As[tig + 4][arow + mt * 16 + 8];
        }
#pragma unroll
        for (int nt = 0; nt < 4; nt++) {
            bfr[nt][0] = BsP[tig    ][bcol + nt * 8];
            bfr[nt][1] = BsP[tig + 4][bcol + nt * 8];
        }
#pragma unroll
        for (int mt = 0; mt < 4; mt++)
#pragma unroll
            for (int nt = 0; nt < 4; nt++) {
                float* dd = acc[mt * 4 + nt];
                asm volatile(
                    "mma.sync.aligned.m16n8k16.row.col.f32.bf16.bf16.f32 "
                    "{%0,%1,%2,%3}, {%4,%5,%6,%7}, {%8,%9}, {%0,%1,%2,%3};"
                    : "+f"(dd[0]), "+f"(dd[1]), "+f"(dd[2]), "+f"(dd[3])
                    : "r"(afr[mt][0]), "r"(afr[mt][1]), "r"(afr[mt][2]), "r"(afr[mt][3]),
                      "r"(bfr[nt][0]), "r"(bfr[nt][1]));
            }
    }

    // ---- epilogue: sum dist^2 * c_cycle^2 (with symmetry) ----
    float part = 0.f;
#pragma unroll
    for (int mt = 0; mt < 4; mt++)
#pragma unroll
        for (int nt = 0; nt < 4; nt++)
#pragma unroll
            for (int rg = 0; rg < 4; rg++) {
                int r = wr * 64 + mt * 16 + gid + ((rg >= 2) ? 8 : 0);
                int c = wc * 32 + nt * 8 + tig * 2 + (rg & 1);
                float dx = sRow[2][r] - sCol[2][c];
                float dy = sRow[3][r] - sCol[3][c];
                float dist = fmaf(dx, dx, dy * dy);
                float gv = acc[mt * 4 + nt][rg];
                float w1 = sRow[0][r] * sCol[1][c] * gv;
                float d2 = dist * dist;
                if (diag) {
                    part = fmaf(d2, w1 * w1, part);
                } else {
                    float w2 = sCol[0][c] * sRow[1][r] * gv;
                    part = fmaf(d2, fmaf(w1, w1, w2 * w2), part);
                }
            }
    red[tid] = part;
    __syncthreads();
    for (int o = 128; o > 0; o >>= 1) {
        if (tid < o) red[tid] += red[tid + o];
        __syncthreads();
    }
    if (tid == 0) g_partial[nm * NPAIR + pr] = red[0];
}

// ---------------- K6: final sqrt + mean ----------------
__global__ void k_final(float* __restrict__ out) {
    int t = threadIdx.x;           // 32 threads, one per nm
    float s = 0.f;
#pragma unroll
    for (int pr = 0; pr < NPAIR; pr++) s += g_partial[t * NPAIR + pr];
    float l = sqrtf(s);
#pragma unroll
    for (int o = 16; o > 0; o >>= 1) l += __shfl_xor_sync(0xffffffffu, l, o);
    if (t == 0) out[0] = l / (float)NM_;
}

// ---------------- launch ----------------
extern "C" void kernel_launch(void* const* d_in, const int* in_sizes, int n_in,
                              void* d_out, int out_size) {
    const float* pix  = (const float*)d_in[0];
    const float* mesh = (const float*)d_in[1];
    const void*  idx  = d_in[2];
    float* out = (float*)d_out;
    (void)in_sizes; (void)n_in; (void)out_size;

    k_detect<<<1, 256>>>((const int*)idx);
    k_sample<<<(N_ * K_ + 255) / 256, 256>>>(pix, idx);
    k_sim<<<dim3(NM_, NCH), 512>>>(mesh);
    k_rowmax<<<(NM_ * K_ + 255) / 256, 256>>>();
    k_rowsum<<<dim3(NM_, NCH), 512>>>();
    k_rowfin<<<(NM_ * K_ + 255) / 256, 256>>>();
    k_colet<<<dim3(NM_, (VP_ + 7) / 8), 256>>>();
    k_gemm<<<dim3(NM_, NPAIR), 256>>>();
    k_final<<<1, 32>>>(out);
}